// round 1
// baseline (speedup 1.0000x reference)
#include <cuda_runtime.h>

// ComponentWiseSpline (rational-quadratic spline flow, forward + log|det J|)
// B=65536 rows, D=128 dims, K=8 bins.
// Strategy:
//   Kernel 1: per-dim table precompute (softmax/cumsum/softplus), 128 threads.
//   Kernel 2: elementwise spline with smem-resident tables, conflict-free
//             [k][d] float4 layout, one warp per row, shuffle-reduce logdet.

#define BB 65536
#define DD 128
#define KK 8

#define WARPS_PER_BLOCK 8
#define ROWS_PER_WARP 8

__device__ float4 gTA[KK * DD];   // {invW, -cw*invW, cumH, H}
__device__ float4 gTB[KK * DD];   // {delta, d0, d1, 0}
__device__ float4 gThrA[DD];      // {cw1+eps, cw2+eps, cw3+eps, cw4+eps}
__device__ float4 gThrB[DD];      // {cw5+eps, cw6+eps, cw7+eps, +INF}

__global__ void precompute_kernel(const float* __restrict__ uw,
                                  const float* __restrict__ uh,
                                  const float* __restrict__ ud) {
    int d = threadIdx.x;
    if (d >= DD) return;
    const float BOUND = 3.0f;
    const float MINW = 1e-3f, MINH = 1e-3f, MIND = 1e-3f, EPS = 1e-6f;

    float w[KK], h[KK];
    // softmax(widths) with max-subtraction (matches jax.nn.softmax)
    float m = -1e30f;
    #pragma unroll
    for (int k = 0; k < KK; k++) { w[k] = uw[d * KK + k]; m = fmaxf(m, w[k]); }
    float s = 0.f;
    #pragma unroll
    for (int k = 0; k < KK; k++) { w[k] = expf(w[k] - m); s += w[k]; }
    float invs = 1.0f / s;
    #pragma unroll
    for (int k = 0; k < KK; k++) w[k] = MINW + (1.0f - MINW * KK) * (w[k] * invs);

    m = -1e30f;
    #pragma unroll
    for (int k = 0; k < KK; k++) { h[k] = uh[d * KK + k]; m = fmaxf(m, h[k]); }
    s = 0.f;
    #pragma unroll
    for (int k = 0; k < KK; k++) { h[k] = expf(h[k] - m); s += h[k]; }
    invs = 1.0f / s;
    #pragma unroll
    for (int k = 0; k < KK; k++) h[k] = MINH + (1.0f - MINH * KK) * (h[k] * invs);

    // knot positions (cumsum, scaled to [-BOUND, BOUND], exact endpoints)
    float cw[KK + 1], ch[KK + 1];
    cw[0] = -BOUND; ch[0] = -BOUND;
    float accw = 0.f, acch = 0.f;
    #pragma unroll
    for (int k = 1; k < KK; k++) {
        accw += w[k - 1]; cw[k] = fmaf(2.0f * BOUND, accw, -BOUND);
        acch += h[k - 1]; ch[k] = fmaf(2.0f * BOUND, acch, -BOUND);
    }
    cw[KK] = BOUND; ch[KK] = BOUND;

    float W[KK], H[KK];
    #pragma unroll
    for (int k = 0; k < KK; k++) { W[k] = cw[k + 1] - cw[k]; H[k] = ch[k + 1] - ch[k]; }

    // derivatives: pad ends with 1 - MIND; interior = MIND + softplus(ud)
    float dv[KK + 1];
    dv[0] = 1.0f - MIND;
    dv[KK] = 1.0f - MIND;
    #pragma unroll
    for (int k = 1; k < KK; k++) {
        float v = ud[d * (KK - 1) + (k - 1)];
        float sp = fmaxf(v, 0.0f) + log1pf(expf(-fabsf(v)));  // stable softplus
        dv[k] = MIND + sp;
    }

    #pragma unroll
    for (int k = 0; k < KK; k++) {
        float invW = 1.0f / W[k];
        float delta = H[k] * invW;
        gTA[k * DD + d] = make_float4(invW, -cw[k] * invW, ch[k], H[k]);
        gTB[k * DD + d] = make_float4(delta, dv[k], dv[k + 1], 0.0f);
    }
    gThrA[d] = make_float4(cw[1] + EPS, cw[2] + EPS, cw[3] + EPS, cw[4] + EPS);
    gThrB[d] = make_float4(cw[5] + EPS, cw[6] + EPS, cw[7] + EPS, 3.402823e38f);
}

__global__ void __launch_bounds__(WARPS_PER_BLOCK * 32)
spline_kernel(const float* __restrict__ x,
              float* __restrict__ uout,
              float* __restrict__ ldout) {
    __shared__ float4 sTA[KK * DD];
    __shared__ float4 sTB[KK * DD];
    __shared__ float4 sThrA[DD];
    __shared__ float4 sThrB[DD];

    int tid = threadIdx.x;
    const int nthr = WARPS_PER_BLOCK * 32;
    for (int i = tid; i < KK * DD; i += nthr) { sTA[i] = gTA[i]; sTB[i] = gTB[i]; }
    if (tid < DD) { sThrA[tid] = gThrA[tid]; sThrB[tid] = gThrB[tid]; }
    __syncthreads();

    int warp = tid >> 5;
    int lane = tid & 31;
    int row0 = (blockIdx.x * WARPS_PER_BLOCK + warp) * ROWS_PER_WARP;

    for (int rr = 0; rr < ROWS_PER_WARP; rr++) {
        int row = row0 + rr;
        const float* xr = x + (size_t)row * DD;
        float* ur = uout + (size_t)row * DD;
        float lsum = 0.f;
        #pragma unroll
        for (int j = 0; j < 4; j++) {
            int d = j * 32 + lane;             // consecutive d across lanes
            float xi = xr[d];
            bool inside = (xi >= -3.0f) && (xi <= 3.0f);
            float xc = fminf(fmaxf(xi, -3.0f), 3.0f);

            float4 tA = sThrA[d];
            float4 tB = sThrB[d];
            int k = (int)(xc >= tA.x) + (int)(xc >= tA.y) + (int)(xc >= tA.z) +
                    (int)(xc >= tA.w) + (int)(xc >= tB.x) + (int)(xc >= tB.y) +
                    (int)(xc >= tB.z);

            float4 a = sTA[k * DD + d];        // {invW, -cw*invW, cumH, H}
            float4 b = sTB[k * DD + d];        // {delta, d0, d1, -}

            float theta = fmaf(xc, a.x, a.y);
            float omt   = 1.0f - theta;
            float t1m   = theta * omt;
            float th2   = theta * theta;

            float num = fmaf(a.w * b.x, th2, a.w * b.y * t1m);        // H*(d*th2 + d0*t1m)
            float e   = b.y + b.z - 2.0f * b.x;                        // d0+d1-2*delta
            float den = fmaf(e, t1m, b.x);
            float invden = __fdividef(1.0f, den);
            float uo = fmaf(num, invden, a.z);

            float dnum = (b.x * b.x) *
                         fmaf(b.z, th2, fmaf(2.0f * b.x, t1m, b.y * omt * omt));
            float lad = __logf(dnum * invden * invden);

            uo  = inside ? uo  : xi;
            lad = inside ? lad : 0.0f;
            ur[d] = uo;
            lsum += lad;
        }
        #pragma unroll
        for (int off = 16; off; off >>= 1)
            lsum += __shfl_xor_sync(0xffffffffu, lsum, off);
        if (lane == 0) ldout[row] = lsum;
    }
}

extern "C" void kernel_launch(void* const* d_in, const int* in_sizes, int n_in,
                              void* d_out, int out_size) {
    const float* x  = (const float*)d_in[0];
    const float* uw = (const float*)d_in[1];
    const float* uh = (const float*)d_in[2];
    const float* ud = (const float*)d_in[3];
    float* out = (float*)d_out;

    precompute_kernel<<<1, DD>>>(uw, uh, ud);

    const int rows_per_block = WARPS_PER_BLOCK * ROWS_PER_WARP;   // 64
    const int nblocks = BB / rows_per_block;                      // 1024
    spline_kernel<<<nblocks, WARPS_PER_BLOCK * 32>>>(
        x, out, out + (size_t)BB * DD);
}